// round 5
// baseline (speedup 1.0000x reference)
#include <cuda_runtime.h>

// ----------------------------------------------------------------------------
// Cross_MultiAttention — algebraically folded, dual-lane (branch-pair) f32x2.
//
// logit_h,br(s,j) = f_br[s] . (M_h @ fcat[j]) + v_h . fcat[j]
// Per head-pass, thread j precomputes into smem:
//   mh[j][k] = sum_c M_h[k][c] fcat[j][c]   (6 scalars, lane-duplicated)
//   c[j]     = v_h . fcat[j]                (lane-duplicated)
//   Fp[j][o] = fcat[j] . P_h[o]             (branch pair in f32x2 lanes)
// j-loop: 6 fma2 logit (f_br register-resident, 6-dim) + ex2 + 6 fma2 accum,
// 104B smem per j.  2 CTAs/SM for latency hiding.
// ----------------------------------------------------------------------------

#define SCALE_EMB 0.044194173824159216f   // 512^-0.5
#define LOG2E     1.4426950408889634f

typedef unsigned long long u64;

struct Params {
    float M[8][6][12];      // LOG2E*SCALE * A_q_h @ A_k_h^T
    float v[8][12];         // LOG2E*SCALE * bq_eff_h @ A_k_h^T
    u64   Pp[8][6][12];     // pack2(P_br1[h][o][c], P_br2[h][o][c])
    float C[6];             // bp + (Wp1+Wp2) @ bv_eff
};

__device__ float g_part[3][8][13][512];   // per-m-chunk partial folds (row12 = bias)
__device__ float g_A[3][13][512];         // folded: [0]=Aq(6)+bqe, [1]=Ak+bke, [2]=Av+bve
__device__ Params g_params;

// ---- packed f32x2 helpers ----
__device__ __forceinline__ u64 pack2(float lo, float hi) {
    u64 r; asm("mov.b64 %0, {%1,%2};" : "=l"(r) : "f"(lo), "f"(hi)); return r;
}
__device__ __forceinline__ void unpack2(u64 v, float& lo, float& hi) {
    asm("mov.b64 {%0,%1}, %2;" : "=f"(lo), "=f"(hi) : "l"(v));
}
__device__ __forceinline__ u64 fma2(u64 a, u64 b, u64 c) {
    u64 d; asm("fma.rn.f32x2 %0, %1, %2, %3;" : "=l"(d) : "l"(a), "l"(b), "l"(c)); return d;
}
__device__ __forceinline__ u64 mul2(u64 a, u64 b) {
    u64 d; asm("mul.rn.f32x2 %0, %1, %2;" : "=l"(d) : "l"(a), "l"(b)); return d;
}
__device__ __forceinline__ u64 add2(u64 a, u64 b) {
    u64 d; asm("add.rn.f32x2 %0, %1, %2;" : "=l"(d) : "l"(a), "l"(b)); return d;
}
__device__ __forceinline__ float ex2f(float x) {
    float y; asm("ex2.approx.ftz.f32 %0, %1;" : "=f"(y) : "f"(x)); return y;
}
__device__ __forceinline__ float rcpf(float x) {
    float y; asm("rcp.approx.ftz.f32 %0, %1;" : "=f"(y) : "f"(x)); return y;
}

// ----------------------------------------------------------------------------
// Precompute 1a: partial fold over a 64-wide m chunk.
// ----------------------------------------------------------------------------
__global__ void fold_partial(const float* __restrict__ W_emb,  const float* __restrict__ b_emb,
                             const float* __restrict__ W_emb2, const float* __restrict__ b_emb2,
                             const float* __restrict__ Wq, const float* __restrict__ Wk,
                             const float* __restrict__ Wv)
{
    int mat = blockIdx.x >> 3, chunk = blockIdx.x & 7;
    const float* We = (mat == 0) ? W_emb : W_emb2;
    const float* be = (mat == 0) ? b_emb : b_emb2;
    const float* W  = (mat == 0) ? Wq : (mat == 1 ? Wk : Wv);
    int R = (mat == 0) ? 6 : 12;

    __shared__ float sE[12][64];
    __shared__ float sb[64];
    int tid = threadIdx.x;
    int mc0 = chunk * 64;
    for (int i = tid; i < R * 64; i += 512) {
        int k = i >> 6, mm = i & 63;
        sE[k][mm] = We[k * 512 + mc0 + mm];
    }
    if (tid < 64) sb[tid] = be[mc0 + tid];
    __syncthreads();

    int e = tid;
    float acc[12];
#pragma unroll
    for (int k = 0; k < 12; k++) acc[k] = 0.f;
    float bacc = 0.f;
    if (R == 6) {
#pragma unroll 8
        for (int mm = 0; mm < 64; mm++) {
            float w = W[(mc0 + mm) * 512 + e];
            bacc += sb[mm] * w;
#pragma unroll
            for (int k = 0; k < 6; k++) acc[k] += sE[k][mm] * w;
        }
    } else {
#pragma unroll 4
        for (int mm = 0; mm < 64; mm++) {
            float w = W[(mc0 + mm) * 512 + e];
            bacc += sb[mm] * w;
#pragma unroll
            for (int k = 0; k < 12; k++) acc[k] += sE[k][mm] * w;
        }
    }
    for (int k = 0; k < R; k++) g_part[mat][chunk][k][e] = acc[k];
    g_part[mat][chunk][12][e] = bacc;
}

// ----------------------------------------------------------------------------
// Precompute 1b: deterministic reduce over the 8 chunks + add projection bias.
// ----------------------------------------------------------------------------
__global__ void fold_reduce(const float* __restrict__ bq, const float* __restrict__ bk,
                            const float* __restrict__ bv)
{
    int t = blockIdx.x * blockDim.x + threadIdx.x;
    if (t >= 3 * 13 * 512) return;
    int mat = t / (13 * 512);
    int r   = (t / 512) % 13;
    int e   = t & 511;
    if (mat == 0 && r >= 6 && r < 12) { g_A[0][r][e] = 0.f; return; }
    float s = 0.f;
#pragma unroll
    for (int c = 0; c < 8; c++) s += g_part[mat][c][r][e];
    if (r == 12) s += (mat == 0 ? bq[e] : (mat == 1 ? bk[e] : bv[e]));
    g_A[mat][r][e] = s;
}

// ----------------------------------------------------------------------------
// Precompute 2: tiny per-head matrices (log2e*SCALE prefolded; P packed).
// ----------------------------------------------------------------------------
__global__ void precompute_small(const float* __restrict__ Wp, const float* __restrict__ bp)
{
    int idx = blockIdx.x * 256 + threadIdx.x;
    const float KS = LOG2E * SCALE_EMB;
    if (idx < 576) {                                   // M[h][k][c]
        int h = idx / 72, r = idx % 72, k = r / 12, c = r % 12;
        float s = 0.f;
#pragma unroll 4
        for (int d = 0; d < 64; d++) s += g_A[0][k][h * 64 + d] * g_A[1][c][h * 64 + d];
        g_params.M[h][k][c] = KS * s;
    } else if (idx < 672) {                            // v[h][c]
        int t = idx - 576, h = t / 12, c = t % 12;
        float s = 0.f;
#pragma unroll 4
        for (int d = 0; d < 64; d++) s += g_A[0][12][h * 64 + d] * g_A[1][c][h * 64 + d];
        g_params.v[h][c] = KS * s;
    } else if (idx < 1248) {                           // Pp[h][o][c] (both branches)
        int t = idx - 672, h = t / 72, q = t % 72, o = q / 12, c = q % 12;
        float s0 = 0.f, s1 = 0.f;
#pragma unroll 4
        for (int d = 0; d < 64; d++) {
            float av = g_A[2][c][h * 64 + d];
            s0 += Wp[o * 1024 +       h * 64 + d] * av;
            s1 += Wp[o * 1024 + 512 + h * 64 + d] * av;
        }
        g_params.Pp[h][o][c] = pack2(s0, s1);
    } else if (idx < 1254) {                           // C[o]
        int o = idx - 1248;
        float s = bp[o];
#pragma unroll 4
        for (int e = 0; e < 512; e++)
            s += (Wp[o * 1024 + e] + Wp[o * 1024 + 512 + e]) * g_A[2][12][e];
        g_params.C[o] = s;
    }
}

// ----------------------------------------------------------------------------
// Main fused kernel: one CTA per 16x16 tile (512 CTAs), one thread per query s.
// 8 passes (one head each); branch pair rides the f32x2 lanes.
// smem row per j per pass: [mh0..5 dup][c dup][Fp0..5][pad] = 14 u64.
// ----------------------------------------------------------------------------
__global__ __launch_bounds__(256, 2)
void cross_attn_main(const float* __restrict__ img1, const float* __restrict__ img2,
                     float* __restrict__ out)
{
    __shared__ __align__(16) u64 sJ[256][14];
    __shared__ Params sp;

    int b  = blockIdx.x;
    int bi = b >> 6, th = (b >> 3) & 7, tw = b & 7;
    int s  = threadIdx.x;
    int y  = s >> 4, x = s & 15;
    int base = bi * 6 * 16384 + (th * 16 + y) * 128 + (tw * 16 + x);

    float fc[12];                       // fcat[s] = [f1(6), f2(6)]
#pragma unroll
    for (int c = 0; c < 6; c++) {
        fc[c]     = img1[base + c * 16384];
        fc[6 + c] = img2[base + c * 16384];
    }
    u64 fdual[6];                       // query features, lanes = (br1, br2)
#pragma unroll
    for (int k = 0; k < 6; k++) fdual[k] = pack2(fc[k], fc[6 + k]);

    {
        float* dst = (float*)&sp;
        const float* src = (const float*)&g_params;
        for (int i = s; i < (int)(sizeof(Params) / 4); i += 256) dst[i] = src[i];
    }
    __syncthreads();

    u64 outacc[6];
#pragma unroll
    for (int o = 0; o < 6; o++) outacc[o] = 0ull;

    for (int h = 0; h < 8; h++) {
        // ---- per-pass setup: thread s fills row s ----
        if (h) __syncthreads();          // prior pass finished reading sJ
#pragma unroll
        for (int k = 0; k < 6; k++) {
            float a = sp.M[h][k][0] * fc[0];
#pragma unroll
            for (int c = 1; c < 12; c++) a += sp.M[h][k][c] * fc[c];
            sJ[s][k] = pack2(a, a);
        }
        {
            float a = sp.v[h][0] * fc[0];
#pragma unroll
            for (int c = 1; c < 12; c++) a += sp.v[h][c] * fc[c];
            sJ[s][6] = pack2(a, a);
        }
#pragma unroll
        for (int o = 0; o < 6; o++) {
            u64 acc = mul2(pack2(fc[0], fc[0]), sp.Pp[h][o][0]);
#pragma unroll
            for (int c = 1; c < 12; c++)
                acc = fma2(pack2(fc[c], fc[c]), sp.Pp[h][o][c], acc);
            sJ[s][7 + o] = acc;
        }
        __syncthreads();

        u64 O[6];
#pragma unroll
        for (int o = 0; o < 6; o++) O[o] = 0ull;
        u64 l = 0ull;

        // Logits are O(0.1) by construction (weights 0.02, folded twice):
        // exp without max-subtraction is exact softmax.
#pragma unroll 2
        for (int j = 0; j < 256; j++) {
            const ulonglong2* rp = (const ulonglong2*)(&sJ[j][0]);
            ulonglong2 r0 = rp[0], r1 = rp[1], r2 = rp[2];
            ulonglong2 r3 = rp[3], r4 = rp[4], r5 = rp[5];
            // r0..r2: mh dup; r3.x: c dup; r3.y..r5.y: Fp[0..4]
            u64 p5 = ((const u64*)(&sJ[j][0]))[12];

            u64 ae = fma2(fdual[0], r0.x, r3.x);
            u64 ao = mul2(fdual[1], r0.y);
            ae = fma2(fdual[2], r1.x, ae);
            ao = fma2(fdual[3], r1.y, ao);
            ae = fma2(fdual[4], r2.x, ae);
            ao = fma2(fdual[5], r2.y, ao);
            u64 a = add2(ae, ao);

            float e0, e1;
            unpack2(a, e0, e1);
            u64 pp = pack2(ex2f(e0), ex2f(e1));
            l = add2(l, pp);

            O[0] = fma2(pp, r3.y, O[0]);
            O[1] = fma2(pp, r4.x, O[1]);
            O[2] = fma2(pp, r4.y, O[2]);
            O[3] = fma2(pp, r5.x, O[3]);
            O[4] = fma2(pp, r5.y, O[4]);
            O[5] = fma2(pp, p5,   O[5]);
        }

        float la, lb;
        unpack2(l, la, lb);
        u64 inv = pack2(rcpf(la), rcpf(lb));
#pragma unroll
        for (int o = 0; o < 6; o++) outacc[o] = fma2(O[o], inv, outacc[o]);
    }

#pragma unroll
    for (int o = 0; o < 6; o++) {
        float lo, hi;
        unpack2(outacc[o], lo, hi);
        out[base + o * 16384] = sp.C[o] + lo + hi;
    }
}

// ----------------------------------------------------------------------------
extern "C" void kernel_launch(void* const* d_in, const int* in_sizes, int n_in,
                              void* d_out, int out_size)
{
    const float* img1   = (const float*)d_in[0];
    const float* img2   = (const float*)d_in[1];
    const float* W_emb  = (const float*)d_in[2];
    const float* b_emb  = (const float*)d_in[3];
    const float* W_emb2 = (const float*)d_in[4];
    const float* b_emb2 = (const float*)d_in[5];
    const float* Wq     = (const float*)d_in[6];
    const float* bq     = (const float*)d_in[7];
    const float* Wk     = (const float*)d_in[8];
    const float* bk     = (const float*)d_in[9];
    const float* Wv     = (const float*)d_in[10];
    const float* bv     = (const float*)d_in[11];
    const float* Wp     = (const float*)d_in[12];
    const float* bp     = (const float*)d_in[13];
    float* out = (float*)d_out;

    fold_partial<<<24, 512>>>(W_emb, b_emb, W_emb2, b_emb2, Wq, Wk, Wv);
    fold_reduce<<<78, 256>>>(bq, bk, bv);
    precompute_small<<<5, 256>>>(Wp, bp);
    cross_attn_main<<<512, 256>>>(img1, img2, out);
}

// round 6
// speedup vs baseline: 1.0733x; 1.0733x over previous
#include <cuda_runtime.h>

// ----------------------------------------------------------------------------
// Cross_MultiAttention — algebraically folded, dual-lane (branch-pair) f32x2.
//
// logit_h,br(s,j) = (f_br[s] @ M_h + v_h) . fcat[j]    (M_h [6,12])
// att@V folds through Wp into per-(head,branch) [6,12] P.
// Structure: 4 passes x 2 heads. fcat duplicated per-lane in smem (one
// broadcast stream, 6 LDS.128/j). Per head: g[12] packed (br1,br2), G[12]
// register accumulators. outacc in smem rows; fc reloaded per pass via LDG
// => <=128 regs => 2 CTAs/SM for fma latency hiding. No syncs in pass loop.
// ----------------------------------------------------------------------------

#define SCALE_EMB 0.044194173824159216f   // 512^-0.5
#define LOG2E     1.4426950408889634f

typedef unsigned long long u64;

struct Params {
    float M[8][6][12];      // LOG2E*SCALE * A_q_h @ A_k_h^T
    float v[8][12];         // LOG2E*SCALE * bq_eff_h @ A_k_h^T
    u64   Pp[8][6][12];     // pack2(P_br1[h][o][c], P_br2[h][o][c])
    float C[6];             // bp + (Wp1+Wp2) @ bv_eff
};

__device__ float g_part[3][8][13][512];   // per-m-chunk partial folds (row12 = bias)
__device__ float g_A[3][13][512];         // folded: [0]=Aq(6)+bqe, [1]=Ak+bke, [2]=Av+bve
__device__ Params g_params;

// ---- packed f32x2 helpers ----
__device__ __forceinline__ u64 pack2(float lo, float hi) {
    u64 r; asm("mov.b64 %0, {%1,%2};" : "=l"(r) : "f"(lo), "f"(hi)); return r;
}
__device__ __forceinline__ void unpack2(u64 v, float& lo, float& hi) {
    asm("mov.b64 {%0,%1}, %2;" : "=f"(lo), "=f"(hi) : "l"(v));
}
__device__ __forceinline__ u64 fma2(u64 a, u64 b, u64 c) {
    u64 d; asm("fma.rn.f32x2 %0, %1, %2, %3;" : "=l"(d) : "l"(a), "l"(b), "l"(c)); return d;
}
__device__ __forceinline__ u64 mul2(u64 a, u64 b) {
    u64 d; asm("mul.rn.f32x2 %0, %1, %2;" : "=l"(d) : "l"(a), "l"(b)); return d;
}
__device__ __forceinline__ u64 add2(u64 a, u64 b) {
    u64 d; asm("add.rn.f32x2 %0, %1, %2;" : "=l"(d) : "l"(a), "l"(b)); return d;
}
__device__ __forceinline__ float ex2f(float x) {
    float y; asm("ex2.approx.ftz.f32 %0, %1;" : "=f"(y) : "f"(x)); return y;
}
__device__ __forceinline__ float rcpf(float x) {
    float y; asm("rcp.approx.ftz.f32 %0, %1;" : "=f"(y) : "f"(x)); return y;
}

// ----------------------------------------------------------------------------
// Precompute 1a: partial fold over a 64-wide m chunk.
// ----------------------------------------------------------------------------
__global__ void fold_partial(const float* __restrict__ W_emb,  const float* __restrict__ b_emb,
                             const float* __restrict__ W_emb2, const float* __restrict__ b_emb2,
                             const float* __restrict__ Wq, const float* __restrict__ Wk,
                             const float* __restrict__ Wv)
{
    int mat = blockIdx.x >> 3, chunk = blockIdx.x & 7;
    const float* We = (mat == 0) ? W_emb : W_emb2;
    const float* be = (mat == 0) ? b_emb : b_emb2;
    const float* W  = (mat == 0) ? Wq : (mat == 1 ? Wk : Wv);
    int R = (mat == 0) ? 6 : 12;

    __shared__ float sE[12][64];
    __shared__ float sb[64];
    int tid = threadIdx.x;
    int mc0 = chunk * 64;
    for (int i = tid; i < R * 64; i += 512) {
        int k = i >> 6, mm = i & 63;
        sE[k][mm] = We[k * 512 + mc0 + mm];
    }
    if (tid < 64) sb[tid] = be[mc0 + tid];
    __syncthreads();

    int e = tid;
    float acc[12];
#pragma unroll
    for (int k = 0; k < 12; k++) acc[k] = 0.f;
    float bacc = 0.f;
    if (R == 6) {
#pragma unroll 8
        for (int mm = 0; mm < 64; mm++) {
            float w = W[(mc0 + mm) * 512 + e];
            bacc += sb[mm] * w;
#pragma unroll
            for (int k = 0; k < 6; k++) acc[k] += sE[k][mm] * w;
        }
    } else {
#pragma unroll 4
        for (int mm = 0; mm < 64; mm++) {
            float w = W[(mc0 + mm) * 512 + e];
            bacc += sb[mm] * w;
#pragma unroll
            for (int k = 0; k < 12; k++) acc[k] += sE[k][mm] * w;
        }
    }
    for (int k = 0; k < R; k++) g_part[mat][chunk][k][e] = acc[k];
    g_part[mat][chunk][12][e] = bacc;
}

// ----------------------------------------------------------------------------
// Precompute 1b: deterministic reduce over the 8 chunks + add projection bias.
// ----------------------------------------------------------------------------
__global__ void fold_reduce(const float* __restrict__ bq, const float* __restrict__ bk,
                            const float* __restrict__ bv)
{
    int t = blockIdx.x * blockDim.x + threadIdx.x;
    if (t >= 3 * 13 * 512) return;
    int mat = t / (13 * 512);
    int r   = (t / 512) % 13;
    int e   = t & 511;
    if (mat == 0 && r >= 6 && r < 12) { g_A[0][r][e] = 0.f; return; }
    float s = 0.f;
#pragma unroll
    for (int c = 0; c < 8; c++) s += g_part[mat][c][r][e];
    if (r == 12) s += (mat == 0 ? bq[e] : (mat == 1 ? bk[e] : bv[e]));
    g_A[mat][r][e] = s;
}

// ----------------------------------------------------------------------------
// Precompute 2: tiny per-head matrices (log2e*SCALE prefolded; P packed).
// ----------------------------------------------------------------------------
__global__ void precompute_small(const float* __restrict__ Wp, const float* __restrict__ bp)
{
    int idx = blockIdx.x * 256 + threadIdx.x;
    const float KS = LOG2E * SCALE_EMB;
    if (idx < 576) {                                   // M[h][k][c]
        int h = idx / 72, r = idx % 72, k = r / 12, c = r % 12;
        float s = 0.f;
#pragma unroll 4
        for (int d = 0; d < 64; d++) s += g_A[0][k][h * 64 + d] * g_A[1][c][h * 64 + d];
        g_params.M[h][k][c] = KS * s;
    } else if (idx < 672) {                            // v[h][c]
        int t = idx - 576, h = t / 12, c = t % 12;
        float s = 0.f;
#pragma unroll 4
        for (int d = 0; d < 64; d++) s += g_A[0][12][h * 64 + d] * g_A[1][c][h * 64 + d];
        g_params.v[h][c] = KS * s;
    } else if (idx < 1248) {                           // Pp[h][o][c] (both branches)
        int t = idx - 672, h = t / 72, q = t % 72, o = q / 12, c = q % 12;
        float s0 = 0.f, s1 = 0.f;
#pragma unroll 4
        for (int d = 0; d < 64; d++) {
            float av = g_A[2][c][h * 64 + d];
            s0 += Wp[o * 1024 +       h * 64 + d] * av;
            s1 += Wp[o * 1024 + 512 + h * 64 + d] * av;
        }
        g_params.Pp[h][o][c] = pack2(s0, s1);
    } else if (idx < 1254) {                           // C[o]
        int o = idx - 1248;
        float s = bp[o];
#pragma unroll 4
        for (int e = 0; e < 512; e++)
            s += (Wp[o * 1024 + e] + Wp[o * 1024 + 512 + e]) * g_A[2][12][e];
        g_params.C[o] = s;
    }
}

// ----------------------------------------------------------------------------
// Main fused kernel: one CTA per 16x16 tile (512 CTAs), one thread per query s.
// ----------------------------------------------------------------------------
__global__ __launch_bounds__(256, 2)
void cross_attn_main(const float* __restrict__ img1, const float* __restrict__ img2,
                     float* __restrict__ out)
{
    __shared__ __align__(16) u64 sFd[256][12];   // fcat dup-lane: (f_c, f_c)
    __shared__ __align__(16) u64 sAcc[256][6];   // per-thread output accumulators
    __shared__ Params sp;

    int b  = blockIdx.x;
    int bi = b >> 6, th = (b >> 3) & 7, tw = b & 7;
    int s  = threadIdx.x;
    int y  = s >> 4, x = s & 15;
    int base = bi * 6 * 16384 + (th * 16 + y) * 128 + (tw * 16 + x);

    {
        float fc0;
#pragma unroll
        for (int c = 0; c < 6; c++) {
            fc0 = img1[base + c * 16384];
            sFd[s][c] = pack2(fc0, fc0);
            fc0 = img2[base + c * 16384];
            sFd[s][6 + c] = pack2(fc0, fc0);
        }
    }
#pragma unroll
    for (int o = 0; o < 6; o++) sAcc[s][o] = 0ull;
    {
        float* dst = (float*)&sp;
        const float* src = (const float*)&g_params;
        for (int i = s; i < (int)(sizeof(Params) / 4); i += 256) dst[i] = src[i];
    }
    __syncthreads();

    for (int hp = 0; hp < 4; hp++) {
        const int h0 = 2 * hp, h1 = h0 + 1;

        // ---- per-pass setup: g (lanes = branches) from reloaded fc ----
        u64 g0[12], g1[12];
        {
            float fc[12];
#pragma unroll
            for (int c = 0; c < 6; c++) {
                fc[c]     = img1[base + c * 16384];
                fc[6 + c] = img2[base + c * 16384];
            }
#pragma unroll
            for (int c = 0; c < 12; c++) {
                float a1 = sp.v[h0][c], a2 = a1;
                float b1 = sp.v[h1][c], b2 = b1;
#pragma unroll
                for (int k = 0; k < 6; k++) {
                    float m0 = sp.M[h0][k][c], m1 = sp.M[h1][k][c];
                    a1 += fc[k] * m0;  a2 += fc[6 + k] * m0;
                    b1 += fc[k] * m1;  b2 += fc[6 + k] * m1;
                }
                g0[c] = pack2(a1, a2);
                g1[c] = pack2(b1, b2);
            }
        }

        u64 G0[12], G1[12];
#pragma unroll
        for (int c = 0; c < 12; c++) { G0[c] = 0ull; G1[c] = 0ull; }
        u64 l0 = 0ull, l1 = 0ull;

        // Logits are O(0.1) by construction (weights 0.02, folded twice):
        // exp without max-subtraction is exact softmax.
#pragma unroll 2
        for (int j = 0; j < 256; j++) {
            const ulonglong2* rp = (const ulonglong2*)(&sFd[j][0]);
            ulonglong2 q0 = rp[0], q1 = rp[1], q2 = rp[2];
            ulonglong2 q3 = rp[3], q4 = rp[4], q5 = rp[5];

            // head0 logit: two half-depth chains
            u64 ae = mul2(g0[0], q0.x);
            u64 ao = mul2(g0[1], q0.y);
            ae = fma2(g0[2],  q1.x, ae);  ao = fma2(g0[3],  q1.y, ao);
            ae = fma2(g0[4],  q2.x, ae);  ao = fma2(g0[5],  q2.y, ao);
            ae = fma2(g0[6],  q3.x, ae);  ao = fma2(g0[7],  q3.y, ao);
            ae = fma2(g0[8],  q4.x, ae);  ao = fma2(g0[9],  q4.y, ao);
            ae = fma2(g0[10], q5.x, ae);  ao = fma2(g0[11], q5.y, ao);
            u64 a0 = add2(ae, ao);
            // head1 logit
            u64 be_ = mul2(g1[0], q0.x);
            u64 bo  = mul2(g1[1], q0.y);
            be_ = fma2(g1[2],  q1.x, be_);  bo = fma2(g1[3],  q1.y, bo);
            be_ = fma2(g1[4],  q2.x, be_);  bo = fma2(g1[5],  q2.y, bo);
            be_ = fma2(g1[6],  q3.x, be_);  bo = fma2(g1[7],  q3.y, bo);
            be_ = fma2(g1[8],  q4.x, be_);  bo = fma2(g1[9],  q4.y, bo);
            be_ = fma2(g1[10], q5.x, be_);  bo = fma2(g1[11], q5.y, bo);
            u64 a1 = add2(be_, bo);

            float e0, e1;
            unpack2(a0, e0, e1);
            u64 pp0 = pack2(ex2f(e0), ex2f(e1));
            unpack2(a1, e0, e1);
            u64 pp1 = pack2(ex2f(e0), ex2f(e1));
            l0 = add2(l0, pp0);
            l1 = add2(l1, pp1);

            G0[0]  = fma2(pp0, q0.x, G0[0]);   G1[0]  = fma2(pp1, q0.x, G1[0]);
            G0[1]  = fma2(pp0, q0.y, G0[1]);   G1[1]  = fma2(pp1, q0.y, G1[1]);
            G0[2]  = fma2(pp0, q1.x, G0[2]);   G1[2]  = fma2(pp1, q1.x, G1[2]);
            G0[3]  = fma2(pp0, q1.y, G0[3]);   G1[3]  = fma2(pp1, q1.y, G1[3]);
            G0[4]  = fma2(pp0, q2.x, G0[4]);   G1[4]  = fma2(pp1, q2.x, G1[4]);
            G0[5]  = fma2(pp0, q2.y, G0[5]);   G1[5]  = fma2(pp1, q2.y, G1[5]);
            G0[6]  = fma2(pp0, q3.x, G0[6]);   G1[6]  = fma2(pp1, q3.x, G1[6]);
            G0[7]  = fma2(pp0, q3.y, G0[7]);   G1[7]  = fma2(pp1, q3.y, G1[7]);
            G0[8]  = fma2(pp0, q4.x, G0[8]);   G1[8]  = fma2(pp1, q4.x, G1[8]);
            G0[9]  = fma2(pp0, q4.y, G0[9]);   G1[9]  = fma2(pp1, q4.y, G1[9]);
            G0[10] = fma2(pp0, q5.x, G0[10]);  G1[10] = fma2(pp1, q5.x, G1[10]);
            G0[11] = fma2(pp0, q5.y, G0[11]);  G1[11] = fma2(pp1, q5.y, G1[11]);
        }

        // ---- epilogue: project unnormalized G through P, scale by 1/l ----
        float la, lb;
        unpack2(l0, la, lb);
        u64 inv0 = pack2(rcpf(la), rcpf(lb));
        unpack2(l1, la, lb);
        u64 inv1 = pack2(rcpf(la), rcpf(lb));
#pragma unroll
        for (int o = 0; o < 6; o++) {
            u64 t0 = mul2(G0[0], sp.Pp[h0][o][0]);
            u64 t1 = mul2(G1[0], sp.Pp[h1][o][0]);
#pragma unroll
            for (int c = 1; c < 12; c++) {
                t0 = fma2(G0[c], sp.Pp[h0][o][c], t0);
                t1 = fma2(G1[c], sp.Pp[h1][o][c], t1);
            }
            u64 acc = sAcc[s][o];
            acc = fma2(t0, inv0, acc);
            acc = fma2(t1, inv1, acc);
            sAcc[s][o] = acc;
        }
    }

#pragma unroll
    for (int o = 0; o < 6; o++) {
        float lo, hi;
        unpack2(sAcc[s][o], lo, hi);
        out[base + o * 16384] = sp.C[o] + lo + hi;
    }
}

// ----------------------------------------------------------------------------
extern "C" void kernel_launch(void* const* d_in, const int* in_sizes, int n_in,
                              void* d_out, int out_size)
{
    const float* img1   = (const float*)d_in[0];
    const float* img2   = (const float*)d_in[1];
    const float* W_emb  = (const float*)d_in[2];
    const float* b_emb  = (const float*)d_in[3];
    const float* W_emb2 = (const float*)d_in[4];
    const float* b_emb2 = (const float*)d_in[5];
    const float* Wq     = (const float*)d_in[6];
    const float* bq     = (const float*)d_in[7];
    const float* Wk     = (const float*)d_in[8];
    const float* bk     = (const float*)d_in[9];
    const float* Wv     = (const float*)d_in[10];
    const float* bv     = (const float*)d_in[11];
    const float* Wp     = (const float*)d_in[12];
    const float* bp     = (const float*)d_in[13];
    float* out = (float*)d_out;

    fold_partial<<<24, 512>>>(W_emb, b_emb, W_emb2, b_emb2, Wq, Wk, Wv);
    fold_reduce<<<78, 256>>>(bq, bk, bv);
    precompute_small<<<5, 256>>>(Wp, bp);
    cross_attn_main<<<512, 256>>>(img1, img2, out);
}

// round 9
// speedup vs baseline: 1.1804x; 1.0997x over previous
#include <cuda_runtime.h>

// ----------------------------------------------------------------------------
// Cross_MultiAttention — algebraically folded.
//
// logit_h,br(s,j) = (f_br[s] @ M_h + v_h) . fcat[j]    (M_h [6,12])
// att@V folds through Wp into per-(head,branch) [6,12] P.
// Loop shape (best measured): pair-packed fcat in smem (48B rows, 3 LDS.128
// per j), one head + both branches per pass, horizontal add for logits,
// pair-packed G accumulators. 2 CTAs/SM enforced; ~95 live regs, no spills.
// ----------------------------------------------------------------------------

#define SCALE_EMB 0.044194173824159216f   // 512^-0.5
#define LOG2E     1.4426950408889634f

typedef unsigned long long u64;

struct Params {
    float M[8][6][12];      // LOG2E*SCALE * A_q_h @ A_k_h^T
    float v[8][12];         // LOG2E*SCALE * bq_eff_h @ A_k_h^T
    float P[2][8][6][12];   // Wp (branch half, head block) @ A_v_h^T
    float C[6];             // bp + (Wp1+Wp2) @ bv_eff
};

__device__ float g_part[3][8][13][512];   // per-m-chunk partial folds (row12 = bias)
__device__ float g_A[3][13][512];         // folded: [0]=Aq(6)+bqe, [1]=Ak+bke, [2]=Av+bve
__device__ Params g_params;

// ---- packed f32x2 helpers ----
__device__ __forceinline__ u64 pack2(float lo, float hi) {
    u64 r; asm("mov.b64 %0, {%1,%2};" : "=l"(r) : "f"(lo), "f"(hi)); return r;
}
__device__ __forceinline__ void unpack2(u64 v, float& lo, float& hi) {
    asm("mov.b64 {%0,%1}, %2;" : "=f"(lo), "=f"(hi) : "l"(v));
}
__device__ __forceinline__ u64 fma2(u64 a, u64 b, u64 c) {
    u64 d; asm("fma.rn.f32x2 %0, %1, %2, %3;" : "=l"(d) : "l"(a), "l"(b), "l"(c)); return d;
}
__device__ __forceinline__ u64 mul2(u64 a, u64 b) {
    u64 d; asm("mul.rn.f32x2 %0, %1, %2;" : "=l"(d) : "l"(a), "l"(b)); return d;
}
__device__ __forceinline__ u64 add2(u64 a, u64 b) {
    u64 d; asm("add.rn.f32x2 %0, %1, %2;" : "=l"(d) : "l"(a), "l"(b)); return d;
}
__device__ __forceinline__ float ex2f(float x) {
    float y; asm("ex2.approx.ftz.f32 %0, %1;" : "=f"(y) : "f"(x)); return y;
}
__device__ __forceinline__ float rcpf(float x) {
    float y; asm("rcp.approx.ftz.f32 %0, %1;" : "=f"(y) : "f"(x)); return y;
}

// ----------------------------------------------------------------------------
// Precompute 1a: partial fold over a 64-wide m chunk.
// ----------------------------------------------------------------------------
__global__ void fold_partial(const float* __restrict__ W_emb,  const float* __restrict__ b_emb,
                             const float* __restrict__ W_emb2, const float* __restrict__ b_emb2,
                             const float* __restrict__ Wq, const float* __restrict__ Wk,
                             const float* __restrict__ Wv)
{
    int mat = blockIdx.x >> 3, chunk = blockIdx.x & 7;
    const float* We = (mat == 0) ? W_emb : W_emb2;
    const float* be = (mat == 0) ? b_emb : b_emb2;
    const float* W  = (mat == 0) ? Wq : (mat == 1 ? Wk : Wv);
    int R = (mat == 0) ? 6 : 12;

    __shared__ float sE[12][64];
    __shared__ float sb[64];
    int tid = threadIdx.x;
    int mc0 = chunk * 64;
    for (int i = tid; i < R * 64; i += 512) {
        int k = i >> 6, mm = i & 63;
        sE[k][mm] = We[k * 512 + mc0 + mm];
    }
    if (tid < 64) sb[tid] = be[mc0 + tid];
    __syncthreads();

    int e = tid;
    float acc[12];
#pragma unroll
    for (int k = 0; k < 12; k++) acc[k] = 0.f;
    float bacc = 0.f;
    if (R == 6) {
#pragma unroll 8
        for (int mm = 0; mm < 64; mm++) {
            float w = W[(mc0 + mm) * 512 + e];
            bacc += sb[mm] * w;
#pragma unroll
            for (int k = 0; k < 6; k++) acc[k] += sE[k][mm] * w;
        }
    } else {
#pragma unroll 4
        for (int mm = 0; mm < 64; mm++) {
            float w = W[(mc0 + mm) * 512 + e];
            bacc += sb[mm] * w;
#pragma unroll
            for (int k = 0; k < 12; k++) acc[k] += sE[k][mm] * w;
        }
    }
    for (int k = 0; k < R; k++) g_part[mat][chunk][k][e] = acc[k];
    g_part[mat][chunk][12][e] = bacc;
}

// ----------------------------------------------------------------------------
// Precompute 1b: deterministic reduce over the 8 chunks + add projection bias.
// ----------------------------------------------------------------------------
__global__ void fold_reduce(const float* __restrict__ bq, const float* __restrict__ bk,
                            const float* __restrict__ bv)
{
    int t = blockIdx.x * blockDim.x + threadIdx.x;
    if (t >= 3 * 13 * 512) return;
    int mat = t / (13 * 512);
    int r   = (t / 512) % 13;
    int e   = t & 511;
    if (mat == 0 && r >= 6 && r < 12) { g_A[0][r][e] = 0.f; return; }
    float s = 0.f;
#pragma unroll
    for (int c = 0; c < 8; c++) s += g_part[mat][c][r][e];
    if (r == 12) s += (mat == 0 ? bq[e] : (mat == 1 ? bk[e] : bv[e]));
    g_A[mat][r][e] = s;
}

// ----------------------------------------------------------------------------
// Precompute 2: tiny per-head matrices (log2e*SCALE prefolded into M, v).
// 1830 work items; grid = 8 x 256.
// ----------------------------------------------------------------------------
__global__ void precompute_small(const float* __restrict__ Wp, const float* __restrict__ bp)
{
    int idx = blockIdx.x * 256 + threadIdx.x;
    const float KS = LOG2E * SCALE_EMB;
    if (idx < 576) {                                   // M[h][k][c]
        int h = idx / 72, r = idx % 72, k = r / 12, c = r % 12;
        float s = 0.f;
#pragma unroll 4
        for (int d = 0; d < 64; d++) s += g_A[0][k][h * 64 + d] * g_A[1][c][h * 64 + d];
        g_params.M[h][k][c] = KS * s;
    } else if (idx < 672) {                            // v[h][c]
        int t = idx - 576, h = t / 12, c = t % 12;
        float s = 0.f;
#pragma unroll 4
        for (int d = 0; d < 64; d++) s += g_A[0][12][h * 64 + d] * g_A[1][c][h * 64 + d];
        g_params.v[h][c] = KS * s;
    } else if (idx < 1824) {                           // P[br][h][o][c]
        int t = idx - 672, br = t / 576, r = t % 576;
        int h = r / 72, q = r % 72, o = q / 12, c = q % 12;
        float s = 0.f;
#pragma unroll 4
        for (int d = 0; d < 64; d++)
            s += Wp[o * 1024 + br * 512 + h * 64 + d] * g_A[2][c][h * 64 + d];
        g_params.P[br][h][o][c] = s;
    } else if (idx < 1830) {                           // C[o]
        int o = idx - 1824;
        float s = bp[o];
#pragma unroll 4
        for (int e = 0; e < 512; e++)
            s += (Wp[o * 1024 + e] + Wp[o * 1024 + 512 + e]) * g_A[2][12][e];
        g_params.C[o] = s;
    }
}

// ----------------------------------------------------------------------------
// Main fused kernel: one CTA per 16x16 tile (512 CTAs), one thread per query s.
// 8 passes (one head, both branches). Pair-packed fcat rows: 48B, 3 LDS.128/j.
// ----------------------------------------------------------------------------
__global__ __launch_bounds__(256, 2)
void cross_attn_main(const float* __restrict__ img1, const float* __restrict__ img2,
                     float* __restrict__ out)
{
    __shared__ __align__(16) u64 sF[256][6];   // pairs (f_{2c}, f_{2c+1}); f1 then f2
    __shared__ Params sp;

    int b  = blockIdx.x;
    int bi = b >> 6, th = (b >> 3) & 7, tw = b & 7;
    int s  = threadIdx.x;
    int y  = s >> 4, x = s & 15;
    int base = bi * 6 * 16384 + (th * 16 + y) * 128 + (tw * 16 + x);

    float f1r[6], f2r[6];
#pragma unroll
    for (int c = 0; c < 6; c++) {
        f1r[c] = img1[base + c * 16384];
        f2r[c] = img2[base + c * 16384];
    }
#pragma unroll
    for (int c = 0; c < 3; c++) {
        sF[s][c]     = pack2(f1r[2 * c], f1r[2 * c + 1]);
        sF[s][3 + c] = pack2(f2r[2 * c], f2r[2 * c + 1]);
    }
    {
        float* dst = (float*)&sp;
        const float* src = (const float*)&g_params;
        for (int i = s; i < (int)(sizeof(Params) / 4); i += 256) dst[i] = src[i];
    }
    __syncthreads();

    float outacc[6];
#pragma unroll
    for (int o = 0; o < 6; o++) outacc[o] = 0.f;

    for (int h = 0; h < 8; h++) {
        // g = (v_h + f_br @ M_h), prescaled by log2e*SCALE, packed over c-pairs
        float g1f[12], g2f[12];
#pragma unroll
        for (int c = 0; c < 12; c++) {
            float a = sp.v[h][c], bb = a;
#pragma unroll
            for (int k = 0; k < 6; k++) {
                float m = sp.M[h][k][c];
                a  += f1r[k] * m;
                bb += f2r[k] * m;
            }
            g1f[c] = a; g2f[c] = bb;
        }
        u64 g1[6], g2[6], G1[6], G2[6];
#pragma unroll
        for (int c = 0; c < 6; c++) {
            g1[c] = pack2(g1f[2 * c], g1f[2 * c + 1]);
            g2[c] = pack2(g2f[2 * c], g2f[2 * c + 1]);
            G1[c] = 0ull; G2[c] = 0ull;
        }
        float l1 = 0.f, l2 = 0.f;

        // Logits are O(0.1) by construction (weights 0.02, folded twice):
        // exp without max-subtraction is exact softmax.
#pragma unroll 2
        for (int j = 0; j < 256; j++) {
            const ulonglong2* rp = (const ulonglong2*)(&sF[j][0]);
            ulonglong2 q0 = rp[0], q1 = rp[1], q2 = rp[2];  // 3x LDS.128 broadcast
            u64 f0 = q0.x, fv1 = q0.y, fv2 = q1.x, f3 = q1.y, f4 = q2.x, f5 = q2.y;

            // branch logits: 2x(3-deep) chains + add2, then horizontal
            u64 a1e = mul2(g1[0], f0);
            u64 a1o = mul2(g1[1], fv1);
            u64 a2e = mul2(g2[0], f0);
            u64 a2o = mul2(g2[1], fv1);
            a1e = fma2(g1[2], fv2, a1e);  a1o = fma2(g1[3], f3, a1o);
            a2e = fma2(g2[2], fv2, a2e);  a2o = fma2(g2[3], f3, a2o);
            a1e = fma2(g1[4], f4,  a1e);  a1o = fma2(g1[5], f5, a1o);
            a2e = fma2(g2[4], f4,  a2e);  a2o = fma2(g2[5], f5, a2o);
            u64 a1 = add2(a1e, a1o);
            u64 a2 = add2(a2e, a2o);

            float lo, hi;
            unpack2(a1, lo, hi); float p1 = ex2f(lo + hi);
            unpack2(a2, lo, hi); float p2 = ex2f(lo + hi);
            l1 += p1; l2 += p2;
            u64 pp1 = pack2(p1, p1), pp2 = pack2(p2, p2);

            G1[0] = fma2(pp1, f0,  G1[0]); G2[0] = fma2(pp2, f0,  G2[0]);
            G1[1] = fma2(pp1, fv1, G1[1]); G2[1] = fma2(pp2, fv1, G2[1]);
            G1[2] = fma2(pp1, fv2, G1[2]); G2[2] = fma2(pp2, fv2, G2[2]);
            G1[3] = fma2(pp1, f3,  G1[3]); G2[3] = fma2(pp2, f3,  G2[3]);
            G1[4] = fma2(pp1, f4,  G1[4]); G2[4] = fma2(pp2, f4,  G2[4]);
            G1[5] = fma2(pp1, f5,  G1[5]); G2[5] = fma2(pp2, f5,  G2[5]);
        }

        float inv1 = rcpf(l1), inv2 = rcpf(l2);
        float Gn1[12], Gn2[12];
#pragma unroll
        for (int c = 0; c < 6; c++) {
            float a, bb;
            unpack2(G1[c], a, bb); Gn1[2 * c] = a * inv1; Gn1[2 * c + 1] = bb * inv1;
            unpack2(G2[c], a, bb); Gn2[2 * c] = a * inv2; Gn2[2 * c + 1] = bb * inv2;
        }
#pragma unroll
        for (int o = 0; o < 6; o++) {
            float acc = outacc[o];
#pragma unroll
            for (int c = 0; c < 12; c++) acc += Gn1[c] * sp.P[0][h][o][c];
#pragma unroll
            for (int c = 0; c < 12; c++) acc += Gn2[c] * sp.P[1][h][o][c];
            outacc[o] = acc;
        }
    }

#pragma unroll
    for (int o = 0; o < 6; o++) out[base + o * 16384] = sp.C[o] + outacc[o];
}

// ----------------------------------------------------------------------------
extern "C" void kernel_launch(void* const* d_in, const int* in_sizes, int n_in,
                              void* d_out, int out_size)
{
    const float* img1   = (const float*)d_in[0];
    const float* img2   = (const float*)d_in[1];
    const float* W_emb  = (const float*)d_in[2];
    const float* b_emb  = (const float*)d_in[3];
    const float* W_emb2 = (const float*)d_in[4];
    const float* b_emb2 = (const float*)d_in[5];
    const float* Wq     = (const float*)d_in[6];
    const float* bq     = (const float*)d_in[7];
    const float* Wk     = (const float*)d_in[8];
    const float* bk     = (const float*)d_in[9];
    const float* Wv     = (const float*)d_in[10];
    const float* bv     = (const float*)d_in[11];
    const float* Wp     = (const float*)d_in[12];
    const float* bp     = (const float*)d_in[13];
    float* out = (float*)d_out;

    fold_partial<<<24, 512>>>(W_emb, b_emb, W_emb2, b_emb2, Wq, Wk, Wv);
    fold_reduce<<<78, 256>>>(bq, bk, bv);
    precompute_small<<<8, 256>>>(Wp, bp);
    cross_attn_main<<<512, 256>>>(img1, img2, out);
}

// round 10
// speedup vs baseline: 1.2443x; 1.0541x over previous
#include <cuda_runtime.h>

// ----------------------------------------------------------------------------
// Cross_MultiAttention — algebraically folded.
//
// logit_h,br(s,j) = (f_br[s] @ M_h + v_h) . fcat[j]    (M_h [6,12])
// att@V folds through Wp into per-(head,branch) [6,12] P.
// Loop shape: pair-packed fcat in smem (48B rows, 3 LDS.128/j), one head +
// both branches per pass, pair-packed G accumulators. Unroll 4 for per-warp
// ILP (the proven lever: R3 vs R9), 2 CTAs/SM, f1r/f2r freed from j-loop
// liveness, packed (l1,l2) accumulator.
// ----------------------------------------------------------------------------

#define SCALE_EMB 0.044194173824159216f   // 512^-0.5
#define LOG2E     1.4426950408889634f

typedef unsigned long long u64;

struct Params {
    float M[8][6][12];      // LOG2E*SCALE * A_q_h @ A_k_h^T
    float v[8][12];         // LOG2E*SCALE * bq_eff_h @ A_k_h^T
    float P[2][8][6][12];   // Wp (branch half, head block) @ A_v_h^T
    float C[6];             // bp + (Wp1+Wp2) @ bv_eff
};

__device__ float g_part[3][8][13][512];   // per-m-chunk partial folds (row12 = bias)
__device__ float g_A[3][13][512];         // folded: [0]=Aq(6)+bqe, [1]=Ak+bke, [2]=Av+bve
__device__ Params g_params;

// ---- packed f32x2 helpers ----
__device__ __forceinline__ u64 pack2(float lo, float hi) {
    u64 r; asm("mov.b64 %0, {%1,%2};" : "=l"(r) : "f"(lo), "f"(hi)); return r;
}
__device__ __forceinline__ void unpack2(u64 v, float& lo, float& hi) {
    asm("mov.b64 {%0,%1}, %2;" : "=f"(lo), "=f"(hi) : "l"(v));
}
__device__ __forceinline__ u64 fma2(u64 a, u64 b, u64 c) {
    u64 d; asm("fma.rn.f32x2 %0, %1, %2, %3;" : "=l"(d) : "l"(a), "l"(b), "l"(c)); return d;
}
__device__ __forceinline__ u64 mul2(u64 a, u64 b) {
    u64 d; asm("mul.rn.f32x2 %0, %1, %2;" : "=l"(d) : "l"(a), "l"(b)); return d;
}
__device__ __forceinline__ u64 add2(u64 a, u64 b) {
    u64 d; asm("add.rn.f32x2 %0, %1, %2;" : "=l"(d) : "l"(a), "l"(b)); return d;
}
__device__ __forceinline__ float ex2f(float x) {
    float y; asm("ex2.approx.ftz.f32 %0, %1;" : "=f"(y) : "f"(x)); return y;
}
__device__ __forceinline__ float rcpf(float x) {
    float y; asm("rcp.approx.ftz.f32 %0, %1;" : "=f"(y) : "f"(x)); return y;
}

// ----------------------------------------------------------------------------
// Precompute 1a: partial fold over a 64-wide m chunk.
// ----------------------------------------------------------------------------
__global__ void fold_partial(const float* __restrict__ W_emb,  const float* __restrict__ b_emb,
                             const float* __restrict__ W_emb2, const float* __restrict__ b_emb2,
                             const float* __restrict__ Wq, const float* __restrict__ Wk,
                             const float* __restrict__ Wv)
{
    int mat = blockIdx.x >> 3, chunk = blockIdx.x & 7;
    const float* We = (mat == 0) ? W_emb : W_emb2;
    const float* be = (mat == 0) ? b_emb : b_emb2;
    const float* W  = (mat == 0) ? Wq : (mat == 1 ? Wk : Wv);
    int R = (mat == 0) ? 6 : 12;

    __shared__ float sE[12][64];
    __shared__ float sb[64];
    int tid = threadIdx.x;
    int mc0 = chunk * 64;
    for (int i = tid; i < R * 64; i += 512) {
        int k = i >> 6, mm = i & 63;
        sE[k][mm] = We[k * 512 + mc0 + mm];
    }
    if (tid < 64) sb[tid] = be[mc0 + tid];
    __syncthreads();

    int e = tid;
    float acc[12];
#pragma unroll
    for (int k = 0; k < 12; k++) acc[k] = 0.f;
    float bacc = 0.f;
    if (R == 6) {
#pragma unroll 8
        for (int mm = 0; mm < 64; mm++) {
            float w = W[(mc0 + mm) * 512 + e];
            bacc += sb[mm] * w;
#pragma unroll
            for (int k = 0; k < 6; k++) acc[k] += sE[k][mm] * w;
        }
    } else {
#pragma unroll 4
        for (int mm = 0; mm < 64; mm++) {
            float w = W[(mc0 + mm) * 512 + e];
            bacc += sb[mm] * w;
#pragma unroll
            for (int k = 0; k < 12; k++) acc[k] += sE[k][mm] * w;
        }
    }
    for (int k = 0; k < R; k++) g_part[mat][chunk][k][e] = acc[k];
    g_part[mat][chunk][12][e] = bacc;
}

// ----------------------------------------------------------------------------
// Precompute 1b: deterministic reduce over the 8 chunks + add projection bias.
// ----------------------------------------------------------------------------
__global__ void fold_reduce(const float* __restrict__ bq, const float* __restrict__ bk,
                            const float* __restrict__ bv)
{
    int t = blockIdx.x * blockDim.x + threadIdx.x;
    if (t >= 3 * 13 * 512) return;
    int mat = t / (13 * 512);
    int r   = (t / 512) % 13;
    int e   = t & 511;
    if (mat == 0 && r >= 6 && r < 12) { g_A[0][r][e] = 0.f; return; }
    float s = 0.f;
#pragma unroll
    for (int c = 0; c < 8; c++) s += g_part[mat][c][r][e];
    if (r == 12) s += (mat == 0 ? bq[e] : (mat == 1 ? bk[e] : bv[e]));
    g_A[mat][r][e] = s;
}

// ----------------------------------------------------------------------------
// Precompute 2: tiny per-head matrices (log2e*SCALE prefolded into M, v).
// ----------------------------------------------------------------------------
__global__ void precompute_small(const float* __restrict__ Wp, const float* __restrict__ bp)
{
    int idx = blockIdx.x * 256 + threadIdx.x;
    const float KS = LOG2E * SCALE_EMB;
    if (idx < 576) {                                   // M[h][k][c]
        int h = idx / 72, r = idx % 72, k = r / 12, c = r % 12;
        float s = 0.f;
#pragma unroll 4
        for (int d = 0; d < 64; d++) s += g_A[0][k][h * 64 + d] * g_A[1][c][h * 64 + d];
        g_params.M[h][k][c] = KS * s;
    } else if (idx < 672) {                            // v[h][c]
        int t = idx - 576, h = t / 12, c = t % 12;
        float s = 0.f;
#pragma unroll 4
        for (int d = 0; d < 64; d++) s += g_A[0][12][h * 64 + d] * g_A[1][c][h * 64 + d];
        g_params.v[h][c] = KS * s;
    } else if (idx < 1824) {                           // P[br][h][o][c]
        int t = idx - 672, br = t / 576, r = t % 576;
        int h = r / 72, q = r % 72, o = q / 12, c = q % 12;
        float s = 0.f;
#pragma unroll 4
        for (int d = 0; d < 64; d++)
            s += Wp[o * 1024 + br * 512 + h * 64 + d] * g_A[2][c][h * 64 + d];
        g_params.P[br][h][o][c] = s;
    } else if (idx < 1830) {                           // C[o]
        int o = idx - 1824;
        float s = bp[o];
#pragma unroll 4
        for (int e = 0; e < 512; e++)
            s += (Wp[o * 1024 + e] + Wp[o * 1024 + 512 + e]) * g_A[2][12][e];
        g_params.C[o] = s;
    }
}

// ----------------------------------------------------------------------------
// Main fused kernel: one CTA per 16x16 tile (512 CTAs), one thread per query s.
// 8 passes (one head, both branches). Pair-packed fcat rows: 48B, 3 LDS.128/j.
// ----------------------------------------------------------------------------
__global__ __launch_bounds__(256, 2)
void cross_attn_main(const float* __restrict__ img1, const float* __restrict__ img2,
                     float* __restrict__ out)
{
    __shared__ __align__(16) u64 sF[256][6];   // pairs (f_{2c}, f_{2c+1}); f1 then f2
    __shared__ Params sp;

    int b  = blockIdx.x;
    int bi = b >> 6, th = (b >> 3) & 7, tw = b & 7;
    int s  = threadIdx.x;
    int y  = s >> 4, x = s & 15;
    int base = bi * 6 * 16384 + (th * 16 + y) * 128 + (tw * 16 + x);

    {
        float a0, a1;
#pragma unroll
        for (int c = 0; c < 3; c++) {
            a0 = img1[base + (2 * c) * 16384];
            a1 = img1[base + (2 * c + 1) * 16384];
            sF[s][c] = pack2(a0, a1);
            a0 = img2[base + (2 * c) * 16384];
            a1 = img2[base + (2 * c + 1) * 16384];
            sF[s][3 + c] = pack2(a0, a1);
        }
    }
    {
        float* dst = (float*)&sp;
        const float* src = (const float*)&g_params;
        for (int i = s; i < (int)(sizeof(Params) / 4); i += 256) dst[i] = src[i];
    }
    __syncthreads();

    float outacc[6];
#pragma unroll
    for (int o = 0; o < 6; o++) outacc[o] = 0.f;

    for (int h = 0; h < 8; h++) {
        // ---- setup: g = v_h + f_br @ M_h (prescaled), fc read from sF ----
        u64 g1[6], g2[6];
        {
            float fc[12];
            const ulonglong2* mp = (const ulonglong2*)(&sF[s][0]);
            ulonglong2 m0 = mp[0], m1 = mp[1], m2 = mp[2];
            unpack2(m0.x, fc[0], fc[1]);   unpack2(m0.y, fc[2], fc[3]);
            unpack2(m1.x, fc[4], fc[5]);   unpack2(m1.y, fc[6], fc[7]);
            unpack2(m2.x, fc[8], fc[9]);   unpack2(m2.y, fc[10], fc[11]);

            float g1f[12], g2f[12];
#pragma unroll
            for (int c = 0; c < 12; c++) {
                float a = sp.v[h][c], bb = a;
#pragma unroll
                for (int k = 0; k < 6; k++) {
                    float m = sp.M[h][k][c];
                    a  += fc[k] * m;
                    bb += fc[6 + k] * m;
                }
                g1f[c] = a; g2f[c] = bb;
            }
#pragma unroll
            for (int c = 0; c < 6; c++) {
                g1[c] = pack2(g1f[2 * c], g1f[2 * c + 1]);
                g2[c] = pack2(g2f[2 * c], g2f[2 * c + 1]);
            }
        }

        u64 G1[6], G2[6];
#pragma unroll
        for (int c = 0; c < 6; c++) { G1[c] = 0ull; G2[c] = 0ull; }
        u64 l12 = 0ull;                 // packed (l1, l2)

        // Logits are O(0.1) by construction (weights 0.02, folded twice):
        // exp without max-subtraction is exact softmax.
#pragma unroll 4
        for (int j = 0; j < 256; j++) {
            const ulonglong2* rp = (const ulonglong2*)(&sF[j][0]);
            ulonglong2 q0 = rp[0], q1 = rp[1], q2 = rp[2];  // 3x LDS.128 broadcast
            u64 f0 = q0.x, fv1 = q0.y, fv2 = q1.x, f3 = q1.y, f4 = q2.x, f5 = q2.y;

            // branch logits: 2x(3-deep) chains + add2, then horizontal
            u64 a1e = mul2(g1[0], f0);
            u64 a1o = mul2(g1[1], fv1);
            u64 a2e = mul2(g2[0], f0);
            u64 a2o = mul2(g2[1], fv1);
            a1e = fma2(g1[2], fv2, a1e);  a1o = fma2(g1[3], f3, a1o);
            a2e = fma2(g2[2], fv2, a2e);  a2o = fma2(g2[3], f3, a2o);
            a1e = fma2(g1[4], f4,  a1e);  a1o = fma2(g1[5], f5, a1o);
            a2e = fma2(g2[4], f4,  a2e);  a2o = fma2(g2[5], f5, a2o);
            u64 a1 = add2(a1e, a1o);
            u64 a2 = add2(a2e, a2o);

            float lo, hi;
            unpack2(a1, lo, hi); float p1 = ex2f(lo + hi);
            unpack2(a2, lo, hi); float p2 = ex2f(lo + hi);
            l12 = add2(l12, pack2(p1, p2));
            u64 pp1 = pack2(p1, p1), pp2 = pack2(p2, p2);

            G1[0] = fma2(pp1, f0,  G1[0]); G2[0] = fma2(pp2, f0,  G2[0]);
            G1[1] = fma2(pp1, fv1, G1[1]); G2[1] = fma2(pp2, fv1, G2[1]);
            G1[2] = fma2(pp1, fv2, G1[2]); G2[2] = fma2(pp2, fv2, G2[2]);
            G1[3] = fma2(pp1, f3,  G1[3]); G2[3] = fma2(pp2, f3,  G2[3]);
            G1[4] = fma2(pp1, f4,  G1[4]); G2[4] = fma2(pp2, f4,  G2[4]);
            G1[5] = fma2(pp1, f5,  G1[5]); G2[5] = fma2(pp2, f5,  G2[5]);
        }

        float l1, l2;
        unpack2(l12, l1, l2);
        float inv1 = rcpf(l1), inv2 = rcpf(l2);
        float Gn1[12], Gn2[12];
#pragma unroll
        for (int c = 0; c < 6; c++) {
            float a, bb;
            unpack2(G1[c], a, bb); Gn1[2 * c] = a * inv1; Gn1[2 * c + 1] = bb * inv1;
            unpack2(G2[c], a, bb); Gn2[2 * c] = a * inv2; Gn2[2 * c + 1] = bb * inv2;
        }
#pragma unroll
        for (int o = 0; o < 6; o++) {
            float acc = outacc[o];
#pragma unroll
            for (int c = 0; c < 12; c++) acc += Gn1[c] * sp.P[0][h][o][c];
#pragma unroll
            for (int c = 0; c < 12; c++) acc += Gn2[c] * sp.P[1][h][o][c];
            outacc[o] = acc;
        }
    }

#pragma unroll
    for (int o = 0; o < 6; o++) out[base + o * 16384] = sp.C[o] + outacc[o];
}

// ----------------------------------------------------------------------------
extern "C" void kernel_launch(void* const* d_in, const int* in_sizes, int n_in,
                              void* d_out, int out_size)
{
    const float* img1   = (const float*)d_in[0];
    const float* img2   = (const float*)d_in[1];
    const float* W_emb  = (const float*)d_in[2];
    const float* b_emb  = (const float*)d_in[3];
    const float* W_emb2 = (const float*)d_in[4];
    const float* b_emb2 = (const float*)d_in[5];
    const float* Wq     = (const float*)d_in[6];
    const float* bq     = (const float*)d_in[7];
    const float* Wk     = (const float*)d_in[8];
    const float* bk     = (const float*)d_in[9];
    const float* Wv     = (const float*)d_in[10];
    const float* bv     = (const float*)d_in[11];
    const float* Wp     = (const float*)d_in[12];
    const float* bp     = (const float*)d_in[13];
    float* out = (float*)d_out;

    fold_partial<<<24, 512>>>(W_emb, b_emb, W_emb2, b_emb2, Wq, Wk, Wv);
    fold_reduce<<<78, 256>>>(bq, bk, bv);
    precompute_small<<<8, 256>>>(Wp, bp);
    cross_attn_main<<<512, 256>>>(img1, img2, out);
}